// round 1
// baseline (speedup 1.0000x reference)
#include <cuda_runtime.h>
#include <cuda_bf16.h>
#include <math.h>

// ---------------- problem constants ----------------
#define BB   2
#define TT   8192
#define DD   1024
#define HH   16
#define HD   64
#define CC   256
#define NC   (TT / CC)          // 32 chunks per (b,h)
#define BT   (BB * TT)          // 16384 rows
#define BH   (BB * HH)          // 32
#define NCH  (BH * NC)          // 1024 chunk units
#define EPS  1e-6f

// ---------------- device scratch (no allocations allowed) ----------------
__device__ float g_qraw[BT * DD];   // reused as "opre" (silu(g)*rmsnorm(o)) later
__device__ float g_kraw[BT * DD];
__device__ float g_vraw[BT * DD];
__device__ float g_gate[BT * DD];
__device__ float g_qh[BT * DD];     // head-major (bh, t, 64), q pre-scaled by d^-0.5
__device__ float g_kh[BT * DD];
__device__ float g_vh[BT * DD];
__device__ float g_gt[BH * TT];     // log-decay per (bh, t)
__device__ float g_bc[BH * TT];     // intra-chunk inclusive cumsum
__device__ float g_Bsum[NCH];       // per-chunk total decay
__device__ float g_kv[NCH * HD * HD];
__device__ float g_Sprev[NCH * HD * HD];

// ---------------- generic fp32 GEMM: C = A(MxK) @ W(KxN), row-major ----------------
__global__ __launch_bounds__(256, 2)
void gemm128(const float* __restrict__ A, const float* __restrict__ W,
             float* __restrict__ C, int M, int N, int K) {
    __shared__ float As[16][132];   // transposed A tile, padded (132*4B keeps 16B align)
    __shared__ float Bs[16][128];

    const int tid = threadIdx.x;
    const int tx = tid & 15;
    const int ty = tid >> 4;
    const int row0 = blockIdx.y * 128;
    const int col0 = blockIdx.x * 128;

    const int ar = tid >> 2;            // 0..63
    const int ac = (tid & 3) << 2;      // 0,4,8,12
    const int br = tid >> 5;            // 0..7
    const int bc = (tid & 31) << 2;     // 0..124

    const float* Aptr = A + (size_t)(row0 + ar) * K + ac;
    const float* Bptr = W + (size_t)br * N + col0 + bc;

    float acc[8][8];
#pragma unroll
    for (int i = 0; i < 8; i++)
#pragma unroll
        for (int j = 0; j < 8; j++) acc[i][j] = 0.f;

    for (int kt = 0; kt < K; kt += 16) {
        float4 a0 = *(const float4*)(Aptr + kt);
        float4 a1 = *(const float4*)(Aptr + (size_t)64 * K + kt);
        float4 b0 = *(const float4*)(Bptr + (size_t)kt * N);
        float4 b1 = *(const float4*)(Bptr + (size_t)(kt + 8) * N);
        __syncthreads();
        As[ac + 0][ar] = a0.x; As[ac + 1][ar] = a0.y;
        As[ac + 2][ar] = a0.z; As[ac + 3][ar] = a0.w;
        As[ac + 0][ar + 64] = a1.x; As[ac + 1][ar + 64] = a1.y;
        As[ac + 2][ar + 64] = a1.z; As[ac + 3][ar + 64] = a1.w;
        *(float4*)&Bs[br][bc] = b0;
        *(float4*)&Bs[br + 8][bc] = b1;
        __syncthreads();
#pragma unroll
        for (int kk = 0; kk < 16; ++kk) {
            float af[8], bf[8];
            *(float4*)(af)     = *(const float4*)&As[kk][ty * 8];
            *(float4*)(af + 4) = *(const float4*)&As[kk][ty * 8 + 4];
            *(float4*)(bf)     = *(const float4*)&Bs[kk][tx * 8];
            *(float4*)(bf + 4) = *(const float4*)&Bs[kk][tx * 8 + 4];
#pragma unroll
            for (int i = 0; i < 8; i++)
#pragma unroll
                for (int j = 0; j < 8; j++)
                    acc[i][j] += af[i] * bf[j];
        }
    }
#pragma unroll
    for (int i = 0; i < 8; i++) {
        size_t r = (size_t)(row0 + ty * 8 + i) * N + col0 + tx * 8;
        *(float4*)&C[r]     = make_float4(acc[i][0], acc[i][1], acc[i][2], acc[i][3]);
        *(float4*)&C[r + 4] = make_float4(acc[i][4], acc[i][5], acc[i][6], acc[i][7]);
    }
}

// ---------------- skinny GEMM: gt = log_sigmoid(x @ Wgt)/16, written (bh, t) ----------------
__global__ __launch_bounds__(256)
void gt_gemm(const float* __restrict__ x, const float* __restrict__ Wgt,
             float* __restrict__ gtout) {
    __shared__ float xs[16][64];
    __shared__ float ws[64][16];
    const int row0 = blockIdx.x * 16;
    const int tid = threadIdx.x;
    const int r = tid >> 4, c = tid & 15;
    const int lr = tid >> 4, lc = (tid & 15) << 2;
    const int wr = tid >> 2, wc = (tid & 3) << 2;
    float acc = 0.f;
    for (int kt = 0; kt < DD; kt += 64) {
        __syncthreads();
        *(float4*)&xs[lr][lc] = *(const float4*)&x[(size_t)(row0 + lr) * DD + kt + lc];
        *(float4*)&ws[wr][wc] = *(const float4*)&Wgt[(size_t)(kt + wr) * HH + wc];
        __syncthreads();
#pragma unroll
        for (int kk = 0; kk < 64; ++kk) acc += xs[r][kk] * ws[kk][c];
    }
    float z = acc;
    float ls = fminf(z, 0.f) - log1pf(expf(-fabsf(z)));   // stable log_sigmoid
    int row = row0 + r;
    int b = row / TT, t = row % TT;
    gtout[((size_t)(b * HH + c)) * TT + t] = ls * (1.f / 16.f);
}

// ---------------- rmsnorm over D=1024 + reorder to head-major ----------------
__global__ __launch_bounds__(256)
void rmsnorm_reorder(const float* __restrict__ src, float* __restrict__ dst,
                     float extra) {
    const int row = blockIdx.x;
    const int b = row / TT, t = row % TT;
    const int tid = threadIdx.x;
    float4 v = *(const float4*)&src[(size_t)row * DD + tid * 4];
    float ss = v.x * v.x + v.y * v.y + v.z * v.z + v.w * v.w;
    __shared__ float red[8];
#pragma unroll
    for (int off = 16; off > 0; off >>= 1)
        ss += __shfl_xor_sync(0xffffffffu, ss, off);
    if ((tid & 31) == 0) red[tid >> 5] = ss;
    __syncthreads();
    float tot = red[0] + red[1] + red[2] + red[3] + red[4] + red[5] + red[6] + red[7];
    float rr = rsqrtf(tot * (1.f / (float)DD) + EPS) * extra;
    int col = tid * 4;
    int h = col >> 6, j = col & 63;
    *(float4*)&dst[((size_t)(b * HH + h) * TT + t) * HD + j] =
        make_float4(v.x * rr, v.y * rr, v.z * rr, v.w * rr);
}

// ---------------- per-chunk inclusive cumsum of gt ----------------
__global__ __launch_bounds__(256)
void cumsum_kernel(const float* __restrict__ gt, float* __restrict__ bc,
                   float* __restrict__ Bsum) {
    const int cid = blockIdx.x;
    const int bh = cid / NC, n = cid % NC;
    const int i = threadIdx.x;
    const size_t idx = (size_t)bh * TT + n * CC + i;
    __shared__ float s[CC];
    s[i] = gt[idx];
    __syncthreads();
    for (int off = 1; off < CC; off <<= 1) {
        float add = (i >= off) ? s[i - off] : 0.f;
        __syncthreads();
        s[i] += add;
        __syncthreads();
    }
    bc[idx] = s[i];
    if (i == CC - 1) Bsum[cid] = s[i];
}

// ---------------- per-chunk kv = (k * exp(B - bc))^T @ v  (64x64) ----------------
__global__ __launch_bounds__(256)
void kv_kernel(const float* __restrict__ kh, const float* __restrict__ vh,
               const float* __restrict__ bc, const float* __restrict__ Bsum,
               float* __restrict__ kv) {
    const int cid = blockIdx.x;
    const int bh = cid / NC, n = cid % NC;
    const size_t tbase = (size_t)bh * TT + n * CC;
    const int tid = threadIdx.x;
    __shared__ float ks[32][64];
    __shared__ float vs[32][64];
    const float Bn = Bsum[cid];
    const int ty = tid >> 4, tx = tid & 15;
    const int tr = tid >> 3, c8 = (tid & 7) << 3;
    float acc[4][4];
#pragma unroll
    for (int i = 0; i < 4; i++)
#pragma unroll
        for (int j = 0; j < 4; j++) acc[i][j] = 0.f;

    for (int ct = 0; ct < 8; ++ct) {
        __syncthreads();
        int trow = ct * 32 + tr;
        float e = expf(Bn - bc[tbase + trow]);
        size_t gb = (tbase + trow) * HD;
        float4 k0 = *(const float4*)&kh[gb + c8];
        float4 k1 = *(const float4*)&kh[gb + c8 + 4];
        *(float4*)&ks[tr][c8]     = make_float4(k0.x * e, k0.y * e, k0.z * e, k0.w * e);
        *(float4*)&ks[tr][c8 + 4] = make_float4(k1.x * e, k1.y * e, k1.z * e, k1.w * e);
        *(float4*)&vs[tr][c8]     = *(const float4*)&vh[gb + c8];
        *(float4*)&vs[tr][c8 + 4] = *(const float4*)&vh[gb + c8 + 4];
        __syncthreads();
#pragma unroll
        for (int kk = 0; kk < 32; ++kk) {
            float4 ka = *(const float4*)&ks[kk][ty * 4];
            float4 vb = *(const float4*)&vs[kk][tx * 4];
            float kaa[4] = {ka.x, ka.y, ka.z, ka.w};
            float vbb[4] = {vb.x, vb.y, vb.z, vb.w};
#pragma unroll
            for (int i = 0; i < 4; i++)
#pragma unroll
                for (int j = 0; j < 4; j++)
                    acc[i][j] += kaa[i] * vbb[j];
        }
    }
    size_t ob = (size_t)cid * HD * HD;
#pragma unroll
    for (int i = 0; i < 4; i++)
        *(float4*)&kv[ob + (size_t)(ty * 4 + i) * HD + tx * 4] =
            make_float4(acc[i][0], acc[i][1], acc[i][2], acc[i][3]);
}

// ---------------- sequential scan over chunks: Sprev[n]=S; S = e^{B_n} S + kv_n ----------------
__global__ __launch_bounds__(256)
void scan_kernel(const float* __restrict__ kv, const float* __restrict__ Bsum,
                 float* __restrict__ Sprev) {
    const int bh = blockIdx.x;
    const int tid = threadIdx.x;
    float4 S[4];
#pragma unroll
    for (int u = 0; u < 4; u++) S[u] = make_float4(0.f, 0.f, 0.f, 0.f);
    for (int n = 0; n < NC; ++n) {
        size_t cb = (size_t)(bh * NC + n) * HD * HD + tid * 16;
#pragma unroll
        for (int u = 0; u < 4; u++) *(float4*)&Sprev[cb + u * 4] = S[u];
        float eB = expf(Bsum[bh * NC + n]);
#pragma unroll
        for (int u = 0; u < 4; u++) {
            float4 kvv = *(const float4*)&kv[cb + u * 4];
            S[u].x = eB * S[u].x + kvv.x;
            S[u].y = eB * S[u].y + kvv.y;
            S[u].z = eB * S[u].z + kvv.z;
            S[u].w = eB * S[u].w + kvv.w;
        }
    }
}

// ---------------- fused intra+cross attention, rmsnorm(d=64), silu(gate)*o ----------------
__global__ __launch_bounds__(256, 1)
void attn_out(const float* __restrict__ qh, const float* __restrict__ kh,
              const float* __restrict__ vh, const float* __restrict__ bc,
              const float* __restrict__ Sprev, const float* __restrict__ gate,
              float* __restrict__ opre) {
    const int cid = blockIdx.x;
    const int bh = cid / NC, n = cid % NC;
    const int b = bh / HH, h = bh % HH;
    const int i = threadIdx.x;                 // one query row per thread
    const size_t tbase = (size_t)bh * TT + n * CC;

    __shared__ float sk[64 * 64];
    __shared__ float sv[64 * 64];
    __shared__ float einv[CC];

    float bci = bc[tbase + i];
    einv[i] = expf(-bci);
    float ebci = expf(bci);

    float4 qv[16];
    {
        const float4* qp = (const float4*)&qh[(tbase + i) * HD];
#pragma unroll
        for (int g = 0; g < 16; g++) {
            float4 q = qp[g];
            qv[g] = make_float4(q.x * ebci, q.y * ebci, q.z * ebci, q.w * ebci);
        }
    }

    // phase 1: state S_{n-1} -> smem, then o_cross = q_scaled @ S
    {
        size_t sb = (size_t)cid * HD * HD + i * 16;
#pragma unroll
        for (int u = 0; u < 4; u++)
            *(float4*)&sk[i * 16 + u * 4] = *(const float4*)&Sprev[sb + u * 4];
    }
    __syncthreads();

    float4 ov[16];
#pragma unroll
    for (int g = 0; g < 16; g++) ov[g] = make_float4(0.f, 0.f, 0.f, 0.f);

#pragma unroll
    for (int mg = 0; mg < 16; ++mg) {
        float qa[4] = {qv[mg].x, qv[mg].y, qv[mg].z, qv[mg].w};
#pragma unroll
        for (int u = 0; u < 4; ++u) {
            float qm = qa[u];
            const float4* Srow = (const float4*)&sk[(mg * 4 + u) * 64];
#pragma unroll
            for (int g = 0; g < 16; ++g) {
                float4 s4 = Srow[g];
                ov[g].x += qm * s4.x; ov[g].y += qm * s4.y;
                ov[g].z += qm * s4.z; ov[g].w += qm * s4.w;
            }
        }
    }

    // phase 2: causal intra-chunk, 4 tiles of 64 k/v rows
    const int tr = i >> 2, cq = (i & 3);
    for (int tile = 0; tile < 4; ++tile) {
        __syncthreads();
        size_t gk = (tbase + tile * 64 + tr) * HD;
#pragma unroll
        for (int u = 0; u < 4; ++u) {
            int cc = (cq + u * 4) * 4;
            *(float4*)&sk[tr * 64 + cc] = *(const float4*)&kh[gk + cc];
            *(float4*)&sv[tr * 64 + cc] = *(const float4*)&vh[gk + cc];
        }
        __syncthreads();
        int base = tile * 64;
        if (i >= base) {
            int lim = i - base; if (lim > 63) lim = 63;
            for (int tt = 0; tt <= lim; ++tt) {
                const float4* kr = (const float4*)&sk[tt * 64];
                float s = 0.f;
#pragma unroll
                for (int g = 0; g < 16; ++g) {
                    float4 k4 = kr[g];
                    s += qv[g].x * k4.x + qv[g].y * k4.y +
                         qv[g].z * k4.z + qv[g].w * k4.w;
                }
                s *= einv[base + tt];
                const float4* vr = (const float4*)&sv[tt * 64];
#pragma unroll
                for (int g = 0; g < 16; ++g) {
                    float4 v4 = vr[g];
                    ov[g].x += s * v4.x; ov[g].y += s * v4.y;
                    ov[g].z += s * v4.z; ov[g].w += s * v4.w;
                }
            }
        }
    }

    // phase 3: rmsnorm over 64, silu(gate)*o, write (b,t,D) layout
    float ss = 0.f;
#pragma unroll
    for (int g = 0; g < 16; ++g)
        ss += ov[g].x * ov[g].x + ov[g].y * ov[g].y +
              ov[g].z * ov[g].z + ov[g].w * ov[g].w;
    float rr = rsqrtf(ss * (1.f / (float)HD) + EPS);

    size_t orow = ((size_t)b * TT + n * CC + i) * DD + h * HD;
#pragma unroll
    for (int g = 0; g < 16; ++g) {
        float4 gg = *(const float4*)&gate[orow + g * 4];
        float sx = gg.x / (1.f + expf(-gg.x));
        float sy = gg.y / (1.f + expf(-gg.y));
        float sz = gg.z / (1.f + expf(-gg.z));
        float sw = gg.w / (1.f + expf(-gg.w));
        *(float4*)&opre[orow + g * 4] =
            make_float4(sx * ov[g].x * rr, sy * ov[g].y * rr,
                        sz * ov[g].z * rr, sw * ov[g].w * rr);
    }
}

// ---------------- host launcher ----------------
static float* devptr(const void* symbol) {
    void* p = nullptr;
    cudaGetSymbolAddress(&p, symbol);
    return (float*)p;
}

extern "C" void kernel_launch(void* const* d_in, const int* in_sizes, int n_in,
                              void* d_out, int out_size) {
    const float* x   = (const float*)d_in[0];
    const float* Wq  = (const float*)d_in[1];
    const float* Wk  = (const float*)d_in[2];
    const float* Wv  = (const float*)d_in[3];
    const float* Wg  = (const float*)d_in[4];
    const float* Wgt = (const float*)d_in[5];
    const float* Wo  = (const float*)d_in[6];
    float* out = (float*)d_out;

    float* qraw = devptr(g_qraw);
    float* kraw = devptr(g_kraw);
    float* vraw = devptr(g_vraw);
    float* gatep = devptr(g_gate);
    float* qhp = devptr(g_qh);
    float* khp = devptr(g_kh);
    float* vhp = devptr(g_vh);
    float* gtp = devptr(g_gt);
    float* bcp = devptr(g_bc);
    float* Bp  = devptr(g_Bsum);
    float* kvp = devptr(g_kv);
    float* Sp  = devptr(g_Sprev);

    dim3 gg(DD / 128, BT / 128);   // (8, 128)

    gemm128<<<gg, 256>>>(x, Wq, qraw, BT, DD, DD);
    gemm128<<<gg, 256>>>(x, Wk, kraw, BT, DD, DD);
    gemm128<<<gg, 256>>>(x, Wv, vraw, BT, DD, DD);
    gemm128<<<gg, 256>>>(x, Wg, gatep, BT, DD, DD);
    gt_gemm<<<BT / 16, 256>>>(x, Wgt, gtp);

    rmsnorm_reorder<<<BT, 256>>>(qraw, qhp, 0.125f);  // fold d^-0.5 into q
    rmsnorm_reorder<<<BT, 256>>>(kraw, khp, 1.f);
    rmsnorm_reorder<<<BT, 256>>>(vraw, vhp, 1.f);

    cumsum_kernel<<<NCH, 256>>>(gtp, bcp, Bp);
    kv_kernel<<<NCH, 256>>>(khp, vhp, bcp, Bp, kvp);
    scan_kernel<<<BH, 256>>>(kvp, Bp, Sp);

    // qraw is dead after reorder: reuse it as the (silu(g)*rmsnorm(o)) buffer
    attn_out<<<NCH, 256>>>(qhp, khp, vhp, bcp, Sp, gatep, qraw);

    gemm128<<<gg, 256>>>(qraw, Wo, out, BT, DD, DD);
}

// round 3
// speedup vs baseline: 1.8322x; 1.8322x over previous
#include <cuda_runtime.h>
#include <cuda_bf16.h>
#include <stdint.h>
#include <math.h>

// ---------------- problem constants ----------------
#define BB   2
#define TT   8192
#define DD   1024
#define HH   16
#define HD   64
#define CC   256
#define NC   (TT / CC)
#define BT   (BB * TT)          // 16384 rows
#define BH   (BB * HH)          // 32
#define NCH  (BH * NC)          // 1024
#define EPS  1e-6f

// ---------------- device scratch ----------------
__device__ float g_qraw[BT * DD];   // later reused as tf32-rounded "opre"
__device__ float g_kraw[BT * DD];
__device__ float g_vraw[BT * DD];
__device__ float g_gate[BT * DD];
__device__ float g_qh[BT * DD];
__device__ float g_kh[BT * DD];
__device__ float g_vh[BT * DD];
__device__ float g_xtf[BT * DD];    // tf32-rounded x
__device__ float g_wtf[5 * DD * DD];// tf32-rounded Wq,Wk,Wv,Wg,Wo
__device__ float g_gt[BH * TT];
__device__ float g_bc[BH * TT];
__device__ float g_Bsum[NCH];
__device__ float g_kv[NCH * HD * HD];
__device__ float g_Sprev[NCH * HD * HD];

__device__ __forceinline__ float tf32r(float x) {
    uint32_t u;
    asm("cvt.rna.tf32.f32 %0, %1;" : "=r"(u) : "f"(x));
    return __uint_as_float(u);
}

// ---------------- tf32 rounding pass (unbiased; removes in-MMA truncation bias) ----
__global__ __launch_bounds__(256)
void round_tf32(const float* __restrict__ in, float* __restrict__ out) {
    size_t i = ((size_t)blockIdx.x * 256 + threadIdx.x) * 4;
    float4 v = *(const float4*)(in + i);
    v.x = tf32r(v.x); v.y = tf32r(v.y); v.z = tf32r(v.z); v.w = tf32r(v.w);
    *(float4*)(out + i) = v;
}

// ---------------- tf32 tensor-core GEMM: C = A(MxK) @ B(KxN) ----------------
#define BM  128
#define BN  128
#define BKK 32
#define AST 36      // A smem row stride (conflict-free fragment loads)
#define BST 132     // B smem row stride

__global__ __launch_bounds__(256, 2)
void gemm_tf32(const float* __restrict__ A, const float* __restrict__ B,
               float* __restrict__ C, int M, int N, int K) {
    extern __shared__ float sm[];
    float* As = sm;                       // [2][BM][AST]
    float* Bs = sm + 2 * BM * AST;        // [2][BKK][BST]

    const int tid  = threadIdx.x;
    const int wid  = tid >> 5, lane = tid & 31;
    const int wm   = wid >> 2, wn   = wid & 3;        // 2 x 4 warp grid
    const int row0 = blockIdx.y * BM, col0 = blockIdx.x * BN;

    const int ar  = tid >> 1;             // 0..127
    const int akq = (tid & 1) * 16;       // k offset 0/16
    const int bk  = tid >> 3;             // 0..31
    const int bnq = (tid & 7) * 16;       // n offset

    const float* Ag = A + (size_t)(row0 + ar) * K + akq;
    const float* Bg = B + (size_t)bk * N + col0 + bnq;

    float acc[4][4][4];
#pragma unroll
    for (int mt = 0; mt < 4; mt++)
#pragma unroll
        for (int nt = 0; nt < 4; nt++)
#pragma unroll
            for (int u = 0; u < 4; u++) acc[mt][nt][u] = 0.f;

    const int NIT = K / BKK;

    // prologue stage into buf 0
    {
        uint32_t abase = (uint32_t)__cvta_generic_to_shared(&As[ar * AST + akq]);
        uint32_t bbase = (uint32_t)__cvta_generic_to_shared(&Bs[bk * BST + bnq]);
#pragma unroll
        for (int u = 0; u < 4; u++)
            asm volatile("cp.async.cg.shared.global [%0], [%1], 16;\n"
                         :: "r"(abase + u * 16), "l"(Ag + u * 4));
#pragma unroll
        for (int u = 0; u < 4; u++)
            asm volatile("cp.async.cg.shared.global [%0], [%1], 16;\n"
                         :: "r"(bbase + u * 16), "l"(Bg + u * 4));
        asm volatile("cp.async.commit_group;\n");
    }

    int buf = 0;
    for (int it = 0; it < NIT; ++it) {
        if (it + 1 < NIT) {
            int kt = (it + 1) * BKK;
            int nb = buf ^ 1;
            uint32_t abase = (uint32_t)__cvta_generic_to_shared(
                &As[nb * BM * AST + ar * AST + akq]);
            uint32_t bbase = (uint32_t)__cvta_generic_to_shared(
                &Bs[nb * BKK * BST + bk * BST + bnq]);
            const float* ag = Ag + kt;
            const float* bg = Bg + (size_t)kt * N;
#pragma unroll
            for (int u = 0; u < 4; u++)
                asm volatile("cp.async.cg.shared.global [%0], [%1], 16;\n"
                             :: "r"(abase + u * 16), "l"(ag + u * 4));
#pragma unroll
            for (int u = 0; u < 4; u++)
                asm volatile("cp.async.cg.shared.global [%0], [%1], 16;\n"
                             :: "r"(bbase + u * 16), "l"(bg + u * 4));
            asm volatile("cp.async.commit_group;\n");
            asm volatile("cp.async.wait_group 1;\n");
        } else {
            asm volatile("cp.async.wait_group 0;\n");
        }
        __syncthreads();

        const float* Ab = As + buf * BM * AST;
        const float* Bb = Bs + buf * BKK * BST;
        const int arow = wm * 64 + (lane >> 2);
        const int bcol = wn * 32 + (lane >> 2);
#pragma unroll
        for (int ks = 0; ks < 4; ++ks) {
            const int acol = ks * 8 + (lane & 3);
            const int brow = ks * 8 + (lane & 3);
            uint32_t af[4][4], bf[4][2];
#pragma unroll
            for (int mt = 0; mt < 4; mt++) {
                const float* p = Ab + (size_t)(arow + mt * 16) * AST + acol;
                af[mt][0] = __float_as_uint(p[0]);
                af[mt][1] = __float_as_uint(p[8 * AST]);
                af[mt][2] = __float_as_uint(p[4]);
                af[mt][3] = __float_as_uint(p[8 * AST + 4]);
            }
#pragma unroll
            for (int nt = 0; nt < 4; nt++) {
                const float* p = Bb + (size_t)brow * BST + bcol + nt * 8;
                bf[nt][0] = __float_as_uint(p[0]);
                bf[nt][1] = __float_as_uint(p[4 * BST]);
            }
#pragma unroll
            for (int mt = 0; mt < 4; mt++)
#pragma unroll
                for (int nt = 0; nt < 4; nt++) {
                    asm volatile(
                        "mma.sync.aligned.m16n8k8.row.col.f32.tf32.tf32.f32 "
                        "{%0,%1,%2,%3}, {%4,%5,%6,%7}, {%8,%9}, {%0,%1,%2,%3};\n"
                        : "+f"(acc[mt][nt][0]), "+f"(acc[mt][nt][1]),
                          "+f"(acc[mt][nt][2]), "+f"(acc[mt][nt][3])
                        : "r"(af[mt][0]), "r"(af[mt][1]),
                          "r"(af[mt][2]), "r"(af[mt][3]),
                          "r"(bf[nt][0]), "r"(bf[nt][1]));
                }
        }
        __syncthreads();
        buf ^= 1;
    }

    const int crow = row0 + wm * 64 + (lane >> 2);
    const int ccol = col0 + wn * 32 + (lane & 3) * 2;
#pragma unroll
    for (int mt = 0; mt < 4; mt++)
#pragma unroll
        for (int nt = 0; nt < 4; nt++) {
            float* p0 = C + (size_t)(crow + mt * 16) * N + ccol + nt * 8;
            float* p1 = p0 + (size_t)8 * N;
            *(float2*)p0 = make_float2(acc[mt][nt][0], acc[mt][nt][1]);
            *(float2*)p1 = make_float2(acc[mt][nt][2], acc[mt][nt][3]);
        }
}

// ---------------- skinny GEMM: gt = log_sigmoid(x @ Wgt)/16 -> (bh, t) ----------------
__global__ __launch_bounds__(256)
void gt_gemm(const float* __restrict__ x, const float* __restrict__ Wgt,
             float* __restrict__ gtout) {
    __shared__ float xs[16][64];
    __shared__ float ws[64][16];
    const int row0 = blockIdx.x * 16;
    const int tid = threadIdx.x;
    const int r = tid >> 4, c = tid & 15;
    const int lr = tid >> 4, lc = (tid & 15) << 2;
    const int wr = tid >> 2, wc = (tid & 3) << 2;
    float acc = 0.f;
    for (int kt = 0; kt < DD; kt += 64) {
        __syncthreads();
        *(float4*)&xs[lr][lc] = *(const float4*)&x[(size_t)(row0 + lr) * DD + kt + lc];
        *(float4*)&ws[wr][wc] = *(const float4*)&Wgt[(size_t)(kt + wr) * HH + wc];
        __syncthreads();
#pragma unroll
        for (int kk = 0; kk < 64; ++kk) acc += xs[r][kk] * ws[kk][c];
    }
    float z = acc;
    float ls = fminf(z, 0.f) - log1pf(expf(-fabsf(z)));
    int row = row0 + r;
    int b = row / TT, t = row % TT;
    gtout[((size_t)(b * HH + c)) * TT + t] = ls * (1.f / 16.f);
}

// ---------------- rmsnorm over D=1024 + reorder to head-major ----------------
__global__ __launch_bounds__(256)
void rmsnorm_reorder(const float* __restrict__ src, float* __restrict__ dst,
                     float extra) {
    const int row = blockIdx.x;
    const int b = row / TT, t = row % TT;
    const int tid = threadIdx.x;
    float4 v = *(const float4*)&src[(size_t)row * DD + tid * 4];
    float ss = v.x * v.x + v.y * v.y + v.z * v.z + v.w * v.w;
    __shared__ float red[8];
#pragma unroll
    for (int off = 16; off > 0; off >>= 1)
        ss += __shfl_xor_sync(0xffffffffu, ss, off);
    if ((tid & 31) == 0) red[tid >> 5] = ss;
    __syncthreads();
    float tot = red[0] + red[1] + red[2] + red[3] + red[4] + red[5] + red[6] + red[7];
    float rr = rsqrtf(tot * (1.f / (float)DD) + EPS) * extra;
    int col = tid * 4;
    int h = col >> 6, j = col & 63;
    *(float4*)&dst[((size_t)(b * HH + h) * TT + t) * HD + j] =
        make_float4(v.x * rr, v.y * rr, v.z * rr, v.w * rr);
}

// ---------------- per-chunk inclusive cumsum of gt ----------------
__global__ __launch_bounds__(256)
void cumsum_kernel(const float* __restrict__ gt, float* __restrict__ bc,
                   float* __restrict__ Bsum) {
    const int cid = blockIdx.x;
    const int bh = cid / NC, n = cid % NC;
    const int i = threadIdx.x;
    const size_t idx = (size_t)bh * TT + n * CC + i;
    __shared__ float s[CC];
    s[i] = gt[idx];
    __syncthreads();
    for (int off = 1; off < CC; off <<= 1) {
        float add = (i >= off) ? s[i - off] : 0.f;
        __syncthreads();
        s[i] += add;
        __syncthreads();
    }
    bc[idx] = s[i];
    if (i == CC - 1) Bsum[cid] = s[i];
}

// ---------------- per-chunk kv = (k * exp(B - bc))^T @ v  (64x64) ----------------
__global__ __launch_bounds__(256)
void kv_kernel(const float* __restrict__ kh, const float* __restrict__ vh,
               const float* __restrict__ bc, const float* __restrict__ Bsum,
               float* __restrict__ kv) {
    const int cid = blockIdx.x;
    const int bh = cid / NC, n = cid % NC;
    const size_t tbase = (size_t)bh * TT + n * CC;
    const int tid = threadIdx.x;
    __shared__ float ks[32][64];
    __shared__ float vs[32][64];
    const float Bn = Bsum[cid];
    const int ty = tid >> 4, tx = tid & 15;
    const int tr = tid >> 3, c8 = (tid & 7) << 3;
    float acc[4][4];
#pragma unroll
    for (int i = 0; i < 4; i++)
#pragma unroll
        for (int j = 0; j < 4; j++) acc[i][j] = 0.f;

    for (int ct = 0; ct < 8; ++ct) {
        __syncthreads();
        int trow = ct * 32 + tr;
        float e = expf(Bn - bc[tbase + trow]);
        size_t gb = (tbase + trow) * HD;
        float4 k0 = *(const float4*)&kh[gb + c8];
        float4 k1 = *(const float4*)&kh[gb + c8 + 4];
        *(float4*)&ks[tr][c8]     = make_float4(k0.x * e, k0.y * e, k0.z * e, k0.w * e);
        *(float4*)&ks[tr][c8 + 4] = make_float4(k1.x * e, k1.y * e, k1.z * e, k1.w * e);
        *(float4*)&vs[tr][c8]     = *(const float4*)&vh[gb + c8];
        *(float4*)&vs[tr][c8 + 4] = *(const float4*)&vh[gb + c8 + 4];
        __syncthreads();
#pragma unroll
        for (int kk = 0; kk < 32; ++kk) {
            float4 ka = *(const float4*)&ks[kk][ty * 4];
            float4 vb = *(const float4*)&vs[kk][tx * 4];
            float kaa[4] = {ka.x, ka.y, ka.z, ka.w};
            float vbb[4] = {vb.x, vb.y, vb.z, vb.w};
#pragma unroll
            for (int i = 0; i < 4; i++)
#pragma unroll
                for (int j = 0; j < 4; j++)
                    acc[i][j] += kaa[i] * vbb[j];
        }
    }
    size_t ob = (size_t)cid * HD * HD;
#pragma unroll
    for (int i = 0; i < 4; i++)
        *(float4*)&kv[ob + (size_t)(ty * 4 + i) * HD + tx * 4] =
            make_float4(acc[i][0], acc[i][1], acc[i][2], acc[i][3]);
}

// ---------------- sequential chunk scan ----------------
__global__ __launch_bounds__(256)
void scan_kernel(const float* __restrict__ kv, const float* __restrict__ Bsum,
                 float* __restrict__ Sprev) {
    const int bh = blockIdx.x;
    const int tid = threadIdx.x;
    float4 S[4];
#pragma unroll
    for (int u = 0; u < 4; u++) S[u] = make_float4(0.f, 0.f, 0.f, 0.f);
    for (int n = 0; n < NC; ++n) {
        size_t cb = (size_t)(bh * NC + n) * HD * HD + tid * 16;
#pragma unroll
        for (int u = 0; u < 4; u++) *(float4*)&Sprev[cb + u * 4] = S[u];
        float eB = expf(Bsum[bh * NC + n]);
#pragma unroll
        for (int u = 0; u < 4; u++) {
            float4 kvv = *(const float4*)&kv[cb + u * 4];
            S[u].x = eB * S[u].x + kvv.x;
            S[u].y = eB * S[u].y + kvv.y;
            S[u].z = eB * S[u].z + kvv.z;
            S[u].w = eB * S[u].w + kvv.w;
        }
    }
}

// ---------------- fused intra+cross attention, rmsnorm(64), silu gate ----------------
__global__ __launch_bounds__(256, 1)
void attn_out(const float* __restrict__ qh, const float* __restrict__ kh,
              const float* __restrict__ vh, const float* __restrict__ bc,
              const float* __restrict__ Sprev, const float* __restrict__ gate,
              float* __restrict__ opre) {
    const int cid = blockIdx.x;
    const int bh = cid / NC, n = cid % NC;
    const int b = bh / HH, h = bh % HH;
    const int i = threadIdx.x;
    const size_t tbase = (size_t)bh * TT + n * CC;

    __shared__ float sk[64 * 64];
    __shared__ float sv[64 * 64];
    __shared__ float einv[CC];

    float bci = bc[tbase + i];
    einv[i] = expf(-bci);
    float ebci = expf(bci);

    float4 qv[16];
    {
        const float4* qp = (const float4*)&qh[(tbase + i) * HD];
#pragma unroll
        for (int g = 0; g < 16; g++) {
            float4 q = qp[g];
            qv[g] = make_float4(q.x * ebci, q.y * ebci, q.z * ebci, q.w * ebci);
        }
    }

    {
        size_t sb = (size_t)cid * HD * HD + i * 16;
#pragma unroll
        for (int u = 0; u < 4; u++)
            *(float4*)&sk[i * 16 + u * 4] = *(const float4*)&Sprev[sb + u * 4];
    }
    __syncthreads();

    float4 ov[16];
#pragma unroll
    for (int g = 0; g < 16; g++) ov[g] = make_float4(0.f, 0.f, 0.f, 0.f);

#pragma unroll
    for (int mg = 0; mg < 16; ++mg) {
        float qa[4] = {qv[mg].x, qv[mg].y, qv[mg].z, qv[mg].w};
#pragma unroll
        for (int u = 0; u < 4; ++u) {
            float qm = qa[u];
            const float4* Srow = (const float4*)&sk[(mg * 4 + u) * 64];
#pragma unroll
            for (int g = 0; g < 16; ++g) {
                float4 s4 = Srow[g];
                ov[g].x += qm * s4.x; ov[g].y += qm * s4.y;
                ov[g].z += qm * s4.z; ov[g].w += qm * s4.w;
            }
        }
    }

    const int tr = i >> 2, cq = (i & 3);
    for (int tile = 0; tile < 4; ++tile) {
        __syncthreads();
        size_t gk = (tbase + tile * 64 + tr) * HD;
#pragma unroll
        for (int u = 0; u < 4; ++u) {
            int cc = (cq + u * 4) * 4;
            *(float4*)&sk[tr * 64 + cc] = *(const float4*)&kh[gk + cc];
            *(float4*)&sv[tr * 64 + cc] = *(const float4*)&vh[gk + cc];
        }
        __syncthreads();
        int base = tile * 64;
        if (i >= base) {
            int lim = i - base; if (lim > 63) lim = 63;
            for (int tt = 0; tt <= lim; ++tt) {
                const float4* kr = (const float4*)&sk[tt * 64];
                float s = 0.f;
#pragma unroll
                for (int g = 0; g < 16; ++g) {
                    float4 k4 = kr[g];
                    s += qv[g].x * k4.x + qv[g].y * k4.y +
                         qv[g].z * k4.z + qv[g].w * k4.w;
                }
                s *= einv[base + tt];
                const float4* vr = (const float4*)&sv[tt * 64];
#pragma unroll
                for (int g = 0; g < 16; ++g) {
                    float4 v4 = vr[g];
                    ov[g].x += s * v4.x; ov[g].y += s * v4.y;
                    ov[g].z += s * v4.z; ov[g].w += s * v4.w;
                }
            }
        }
    }

    float ss = 0.f;
#pragma unroll
    for (int g = 0; g < 16; ++g)
        ss += ov[g].x * ov[g].x + ov[g].y * ov[g].y +
              ov[g].z * ov[g].z + ov[g].w * ov[g].w;
    float rr = rsqrtf(ss * (1.f / (float)HD) + EPS);

    size_t orow = ((size_t)b * TT + n * CC + i) * DD + h * HD;
#pragma unroll
    for (int g = 0; g < 16; ++g) {
        float4 gg = *(const float4*)&gate[orow + g * 4];
        float sx = gg.x / (1.f + expf(-gg.x));
        float sy = gg.y / (1.f + expf(-gg.y));
        float sz = gg.z / (1.f + expf(-gg.z));
        float sw = gg.w / (1.f + expf(-gg.w));
        // pre-round to tf32 so the final MMA GEMM sees exact tf32 operands
        *(float4*)&opre[orow + g * 4] =
            make_float4(tf32r(sx * ov[g].x * rr), tf32r(sy * ov[g].y * rr),
                        tf32r(sz * ov[g].z * rr), tf32r(sw * ov[g].w * rr));
    }
}

// ---------------- host launcher ----------------
static float* devptr(const void* symbol) {
    void* p = nullptr;
    cudaGetSymbolAddress(&p, symbol);
    return (float*)p;
}

extern "C" void kernel_launch(void* const* d_in, const int* in_sizes, int n_in,
                              void* d_out, int out_size) {
    const float* x   = (const float*)d_in[0];
    const float* Wq  = (const float*)d_in[1];
    const float* Wk  = (const float*)d_in[2];
    const float* Wv  = (const float*)d_in[3];
    const float* Wg  = (const float*)d_in[4];
    const float* Wgt = (const float*)d_in[5];
    const float* Wo  = (const float*)d_in[6];
    float* out = (float*)d_out;

    float* qraw  = devptr(g_qraw);
    float* kraw  = devptr(g_kraw);
    float* vraw  = devptr(g_vraw);
    float* gatep = devptr(g_gate);
    float* qhp = devptr(g_qh);
    float* khp = devptr(g_kh);
    float* vhp = devptr(g_vh);
    float* xtf = devptr(g_xtf);
    float* wtf = devptr(g_wtf);
    float* gtp = devptr(g_gt);
    float* bcp = devptr(g_bc);
    float* Bp  = devptr(g_Bsum);
    float* kvp = devptr(g_kv);
    float* Sp  = devptr(g_Sprev);

    const int SMEM = (2 * BM * AST + 2 * BKK * BST) * 4;   // 70656 B
    cudaFuncSetAttribute(gemm_tf32, cudaFuncAttributeMaxDynamicSharedMemorySize, SMEM);

    // pre-round operands to tf32 (rna)
    round_tf32<<<(BT * DD / 4) / 256, 256>>>(x, xtf);
    round_tf32<<<(DD * DD / 4) / 256, 256>>>(Wq, wtf + 0 * DD * DD);
    round_tf32<<<(DD * DD / 4) / 256, 256>>>(Wk, wtf + 1 * DD * DD);
    round_tf32<<<(DD * DD / 4) / 256, 256>>>(Wv, wtf + 2 * DD * DD);
    round_tf32<<<(DD * DD / 4) / 256, 256>>>(Wg, wtf + 3 * DD * DD);
    round_tf32<<<(DD * DD / 4) / 256, 256>>>(Wo, wtf + 4 * DD * DD);

    dim3 gg(DD / BN, BT / BM);   // (8, 128)

    gemm_tf32<<<gg, 256, SMEM>>>(xtf, wtf + 0 * DD * DD, qraw, BT, DD, DD);
    gemm_tf32<<<gg, 256, SMEM>>>(xtf, wtf + 1 * DD * DD, kraw, BT, DD, DD);
    gemm_tf32<<<gg, 256, SMEM>>>(xtf, wtf + 2 * DD * DD, vraw, BT, DD, DD);
    gemm_tf32<<<gg, 256, SMEM>>>(xtf, wtf + 3 * DD * DD, gatep, BT, DD, DD);
    gt_gemm<<<BT / 16, 256>>>(x, Wgt, gtp);

    rmsnorm_reorder<<<BT, 256>>>(qraw, qhp, 0.125f);
    rmsnorm_reorder<<<BT, 256>>>(kraw, khp, 1.f);
    rmsnorm_reorder<<<BT, 256>>>(vraw, vhp, 1.f);

    cumsum_kernel<<<NCH, 256>>>(gtp, bcp, Bp);
    kv_kernel<<<NCH, 256>>>(khp, vhp, bcp, Bp, kvp);
    scan_kernel<<<BH, 256>>>(kvp, Bp, Sp);

    attn_out<<<NCH, 256>>>(qhp, khp, vhp, bcp, Sp, gatep, qraw);

    gemm_tf32<<<gg, 256, SMEM>>>(qraw, wtf + 4 * DD * DD, out, BT, DD, DD);
}

// round 5
// speedup vs baseline: 1.8704x; 1.0208x over previous
#include <cuda_runtime.h>
#include <cuda_bf16.h>
#include <stdint.h>
#include <math.h>

// ---------------- problem constants ----------------
#define BB   2
#define TT   8192
#define DD   1024
#define HH   16
#define HD   64
#define CC   256
#define NC   (TT / CC)
#define BT   (BB * TT)          // 16384 rows
#define BH   (BB * HH)          // 32
#define NCH  (BH * NC)          // 1024
#define EPS  1e-6f

// ---------------- device scratch ----------------
__device__ float g_qkvg[BT * 4 * DD];  // fused q|k|v|g GEMM output, row stride 4096
__device__ float g_qh[BT * DD];
__device__ float g_kh[BT * DD];
__device__ float g_vh[BT * DD];
__device__ float g_xtf[BT * DD];       // tf32-rounded x; reused later as "opre"
__device__ float g_wtf[5 * DD * DD];   // tf32-rounded TRANSPOSED Wq,Wk,Wv,Wg,Wo [N,K]
__device__ float g_gt[BH * TT];
__device__ float g_bc[BH * TT];
__device__ float g_Bsum[NCH];
__device__ float g_kv[NCH * HD * HD];
__device__ float g_Sprev[NCH * HD * HD];

__device__ __forceinline__ float tf32r(float x) {
    uint32_t u;
    asm("cvt.rna.tf32.f32 %0, %1;" : "=r"(u) : "f"(x));
    return __uint_as_float(u);
}

// ---------------- tf32 tensor-core GEMM: C = A(MxK) @ Bt(NxK)^T ----------------
// CTA tile 128x256, warp tile 64x64, K staged 32 at a time, cp.async double buffer.
#define BM  128
#define BN  256
#define BKK 32
#define AST 36      // A smem row stride (floats) — conflict-free fragments
#define BST 260     // B smem row stride (floats) — conflict-free fragments
#define SMEM_GEMM ((2 * BM * AST + 2 * BKK * BST) * 4)   // 103424 B

__global__ __launch_bounds__(256, 1)
void gemm_tf32(const float* __restrict__ A, const float* __restrict__ Bt,
               float* __restrict__ C, int M, int N, int K) {
    extern __shared__ float sm[];
    float* As = sm;                        // [2][BM][AST]
    float* Bs = sm + 2 * BM * AST;         // [2][BKK][BST]

    const int tid  = threadIdx.x;
    const int wid  = tid >> 5, lane = tid & 31;
    const int wm   = wid >> 2, wn   = wid & 3;          // 2 x 4 warps
    const int row0 = blockIdx.y * BM, col0 = blockIdx.x * BN;

    // staging indices
    const int ar  = tid >> 1;              // 0..127 (A row)
    const int akq = (tid & 1) * 16;        // k offset 0/16
    const int bk  = tid >> 3;              // 0..31 (B k-row)
    const int bnq = (tid & 7) * 32;        // n offset 0..224

    const float* Ag = A  + (size_t)(row0 + ar) * K + akq;
    const float* Bg = Bt + (size_t)(col0 + bk) * 0;     // unused base; real addressing below
    const float* Bgr = Bt + (size_t)bk * K;             // note: Bt is [N,K]; we need rows of k!
    // Bt layout is [N][K]; the smem tile Bs[k][n] needs element Bt[n][k].
    // Stage by n: thread covers n = bnq..bnq+31 at k-row bk? That would be 32 strided loads.
    // Instead stage by k-major global reads: we read Bt[col0+nr][kt+kc] contiguous in K.
    (void)Bg; (void)Bgr;

    // B staging (K-contiguous): thread handles n-row nr = tid>>1 (0..127) plus nr+128,
    // k offset bkq = (tid&1)*16; stores TRANSPOSED into Bs[k][n].
    const int nr  = tid >> 1;
    const int bkq = (tid & 1) * 16;
    const float* Bg0 = Bt + (size_t)(col0 + nr) * K + bkq;
    const float* Bg1 = Bt + (size_t)(col0 + 128 + nr) * K + bkq;

    float acc[4][8][4];
#pragma unroll
    for (int mt = 0; mt < 4; mt++)
#pragma unroll
        for (int nt = 0; nt < 8; nt++)
#pragma unroll
            for (int u = 0; u < 4; u++) acc[mt][nt][u] = 0.f;

    const int NIT = K / BKK;

    // prologue: stage tile 0 into buffer 0
    {
        uint32_t abase = (uint32_t)__cvta_generic_to_shared(&As[ar * AST + akq]);
#pragma unroll
        for (int u = 0; u < 4; u++)
            asm volatile("cp.async.cg.shared.global [%0], [%1], 16;"
                         :: "r"(abase + u * 16), "l"(Ag + u * 4));
        // B: load 16 k-values of one n, scatter as 16 scalar STS? No —
        // use cp.async per 4 floats into a k-major *staging* is impossible
        // without transpose. Instead load via LDG and store transposed with STS.
        float4 b0a = *(const float4*)(Bg0);
        float4 b0b = *(const float4*)(Bg0 + 4);
        float4 b0c = *(const float4*)(Bg0 + 8);
        float4 b0d = *(const float4*)(Bg0 + 12);
        float4 b1a = *(const float4*)(Bg1);
        float4 b1b = *(const float4*)(Bg1 + 4);
        float4 b1c = *(const float4*)(Bg1 + 8);
        float4 b1d = *(const float4*)(Bg1 + 12);
        float bv0[16] = {b0a.x,b0a.y,b0a.z,b0a.w, b0b.x,b0b.y,b0b.z,b0b.w,
                         b0c.x,b0c.y,b0c.z,b0c.w, b0d.x,b0d.y,b0d.z,b0d.w};
        float bv1[16] = {b1a.x,b1a.y,b1a.z,b1a.w, b1b.x,b1b.y,b1b.z,b1b.w,
                         b1c.x,b1c.y,b1c.z,b1c.w, b1d.x,b1d.y,b1d.z,b1d.w};
#pragma unroll
        for (int kk = 0; kk < 16; kk++) {
            Bs[(bkq + kk) * BST + nr] = bv0[kk];
            Bs[(bkq + kk) * BST + 128 + nr] = bv1[kk];
        }
        asm volatile("cp.async.commit_group;");
    }

    int buf = 0;
    for (int it = 0; it < NIT; ++it) {
        // prefetch next tile into other buffer
        if (it + 1 < NIT) {
            const int kt = (it + 1) * BKK;
            const int nb = buf ^ 1;
            uint32_t abase = (uint32_t)__cvta_generic_to_shared(
                &As[nb * BM * AST + ar * AST + akq]);
#pragma unroll
            for (int u = 0; u < 4; u++)
                asm volatile("cp.async.cg.shared.global [%0], [%1], 16;"
                             :: "r"(abase + u * 16), "l"(Ag + kt + u * 4));
            float4 b0a = *(const float4*)(Bg0 + kt);
            float4 b0b = *(const float4*)(Bg0 + kt + 4);
            float4 b0c = *(const float4*)(Bg0 + kt + 8);
            float4 b0d = *(const float4*)(Bg0 + kt + 12);
            float4 b1a = *(const float4*)(Bg1 + kt);
            float4 b1b = *(const float4*)(Bg1 + kt + 4);
            float4 b1c = *(const float4*)(Bg1 + kt + 8);
            float4 b1d = *(const float4*)(Bg1 + kt + 12);
            asm volatile("cp.async.commit_group;");
            asm volatile("cp.async.wait_group 1;");
            __syncthreads();      // buffer `buf` ready (its cp.async drained)

            // compute on buf while next-B STS happen after compute? No:
            // we must store next-B before using nb. Store now into nb.
            float* Bn = Bs + nb * BKK * BST;
            float bv0[16] = {b0a.x,b0a.y,b0a.z,b0a.w, b0b.x,b0b.y,b0b.z,b0b.w,
                             b0c.x,b0c.y,b0c.z,b0c.w, b0d.x,b0d.y,b0d.z,b0d.w};
            float bv1[16] = {b1a.x,b1a.y,b1a.z,b1a.w, b1b.x,b1b.y,b1b.z,b1b.w,
                             b1c.x,b1c.y,b1c.z,b1c.w, b1d.x,b1d.y,b1d.z,b1d.w};
#pragma unroll
            for (int kk = 0; kk < 16; kk++) {
                Bn[(bkq + kk) * BST + nr] = bv0[kk];
                Bn[(bkq + kk) * BST + 128 + nr] = bv1[kk];
            }
        } else {
            asm volatile("cp.async.wait_group 0;");
            __syncthreads();
        }

        const float* Ab = As + buf * BM * AST;
        const float* Bb = Bs + buf * BKK * BST;
        const int arow = wm * 64 + (lane >> 2);
        const int bcol = wn * 64 + (lane >> 2);
#pragma unroll
        for (int ks = 0; ks < 4; ++ks) {
            const int acol = ks * 8 + (lane & 3);
            const int brow = ks * 8 + (lane & 3);
            uint32_t af[4][4], bf[8][2];
#pragma unroll
            for (int mt = 0; mt < 4; mt++) {
                const float* p = Ab + (size_t)(arow + mt * 16) * AST + acol;
                af[mt][0] = __float_as_uint(p[0]);
                af[mt][1] = __float_as_uint(p[8 * AST]);
                af[mt][2] = __float_as_uint(p[4]);
                af[mt][3] = __float_as_uint(p[8 * AST + 4]);
            }
#pragma unroll
            for (int nt = 0; nt < 8; nt++) {
                const float* p = Bb + (size_t)brow * BST + bcol + nt * 8;
                bf[nt][0] = __float_as_uint(p[0]);
                bf[nt][1] = __float_as_uint(p[4 * BST]);
            }
#pragma unroll
            for (int mt = 0; mt < 4; mt++)
#pragma unroll
                for (int nt = 0; nt < 8; nt++) {
                    asm volatile(
                        "mma.sync.aligned.m16n8k8.row.col.f32.tf32.tf32.f32 "
                        "{%0,%1,%2,%3}, {%4,%5,%6,%7}, {%8,%9}, {%0,%1,%2,%3};\n"
                        : "+f"(acc[mt][nt][0]), "+f"(acc[mt][nt][1]),
                          "+f"(acc[mt][nt][2]), "+f"(acc[mt][nt][3])
                        : "r"(af[mt][0]), "r"(af[mt][1]),
                          "r"(af[mt][2]), "r"(af[mt][3]),
                          "r"(bf[nt][0]), "r"(bf[nt][1]));
                }
        }
        __syncthreads();
        buf ^= 1;
    }

    const int crow = row0 + wm * 64 + (lane >> 2);
    const int ccol = col0 + wn * 64 + (lane & 3) * 2;
#pragma unroll
    for (int mt = 0; mt < 4; mt++)
#pragma unroll
        for (int nt = 0; nt < 8; nt++) {
            float* p0 = C + (size_t)(crow + mt * 16) * N + ccol + nt * 8;
            float* p1 = p0 + (size_t)8 * N;
            *(float2*)p0 = make_float2(acc[mt][nt][0], acc[mt][nt][1]);
            *(float2*)p1 = make_float2(acc[mt][nt][2], acc[mt][nt][3]);
        }
}

// ---------------- prep: round x to tf32 ----------------
__global__ __launch_bounds__(256)
void round_tf32(const float* __restrict__ in, float* __restrict__ out) {
    size_t i = ((size_t)blockIdx.x * 256 + threadIdx.x) * 4;
    float4 v = *(const float4*)(in + i);
    v.x = tf32r(v.x); v.y = tf32r(v.y); v.z = tf32r(v.z); v.w = tf32r(v.w);
    *(float4*)(out + i) = v;
}

// ---------------- prep: transpose + round weight (1024x1024) ----------------
__global__ __launch_bounds__(256)
void round_tr(const float* __restrict__ W, float* __restrict__ Wt) {
    __shared__ float t[32][33];
    const int bx = blockIdx.x * 32, by = blockIdx.y * 32;
    const int x = threadIdx.x & 31, y = threadIdx.x >> 5;   // 32 x 8
#pragma unroll
    for (int j = 0; j < 32; j += 8)
        t[y + j][x] = W[(size_t)(by + y + j) * DD + bx + x];
    __syncthreads();
#pragma unroll
    for (int j = 0; j < 32; j += 8)
        Wt[(size_t)(bx + y + j) * DD + by + x] = tf32r(t[x][y + j]);
}

// ---------------- skinny GEMM: gt = log_sigmoid(x @ Wgt)/16 -> (bh, t) ----------------
__global__ __launch_bounds__(256)
void gt_gemm(const float* __restrict__ x, const float* __restrict__ Wgt,
             float* __restrict__ gtout) {
    __shared__ float xs[16][64];
    __shared__ float ws[64][16];
    const int row0 = blockIdx.x * 16;
    const int tid = threadIdx.x;
    const int r = tid >> 4, c = tid & 15;
    const int lr = tid >> 4, lc = (tid & 15) << 2;
    const int wr = tid >> 2, wc = (tid & 3) << 2;
    float acc = 0.f;
    for (int kt = 0; kt < DD; kt += 64) {
        __syncthreads();
        *(float4*)&xs[lr][lc] = *(const float4*)&x[(size_t)(row0 + lr) * DD + kt + lc];
        *(float4*)&ws[wr][wc] = *(const float4*)&Wgt[(size_t)(kt + wr) * HH + wc];
        __syncthreads();
#pragma unroll
        for (int kk = 0; kk < 64; ++kk) acc += xs[r][kk] * ws[kk][c];
    }
    float z = acc;
    float ls = fminf(z, 0.f) - log1pf(expf(-fabsf(z)));
    int row = row0 + r;
    int b = row / TT, t = row % TT;
    gtout[((size_t)(b * HH + c)) * TT + t] = ls * (1.f / 16.f);
}

// ---------------- rmsnorm over D=1024 (strided src) + reorder to head-major ------
__global__ __launch_bounds__(256)
void rmsnorm_reorder(const float* __restrict__ src, float* __restrict__ dst,
                     float extra) {
    const int row = blockIdx.x;
    const int b = row / TT, t = row % TT;
    const int tid = threadIdx.x;
    // src row stride is 4*DD (fused qkvg buffer); caller passes base + which*DD
    float4 v = *(const float4*)&src[(size_t)row * (4 * DD) + tid * 4];
    float ss = v.x * v.x + v.y * v.y + v.z * v.z + v.w * v.w;
    __shared__ float red[8];
#pragma unroll
    for (int off = 16; off > 0; off >>= 1)
        ss += __shfl_xor_sync(0xffffffffu, ss, off);
    if ((tid & 31) == 0) red[tid >> 5] = ss;
    __syncthreads();
    float tot = red[0] + red[1] + red[2] + red[3] + red[4] + red[5] + red[6] + red[7];
    float rr = rsqrtf(tot * (1.f / (float)DD) + EPS) * extra;
    int col = tid * 4;
    int h = col >> 6, j = col & 63;
    *(float4*)&dst[((size_t)(b * HH + h) * TT + t) * HD + j] =
        make_float4(v.x * rr, v.y * rr, v.z * rr, v.w * rr);
}

// ---------------- per-chunk inclusive cumsum of gt ----------------
__global__ __launch_bounds__(256)
void cumsum_kernel(const float* __restrict__ gt, float* __restrict__ bc,
                   float* __restrict__ Bsum) {
    const int cid = blockIdx.x;
    const int bh = cid / NC, n = cid % NC;
    const int i = threadIdx.x;
    const size_t idx = (size_t)bh * TT + n * CC + i;
    __shared__ float s[CC];
    s[i] = gt[idx];
    __syncthreads();
    for (int off = 1; off < CC; off <<= 1) {
        float add = (i >= off) ? s[i - off] : 0.f;
        __syncthreads();
        s[i] += add;
        __syncthreads();
    }
    bc[idx] = s[i];
    if (i == CC - 1) Bsum[cid] = s[i];
}

// ---------------- per-chunk kv = (k * exp(B - bc))^T @ v  (64x64) ----------------
__global__ __launch_bounds__(256)
void kv_kernel(const float* __restrict__ kh, const float* __restrict__ vh,
               const float* __restrict__ bc, const float* __restrict__ Bsum,
               float* __restrict__ kv) {
    const int cid = blockIdx.x;
    const int bh = cid / NC, n = cid % NC;
    const size_t tbase = (size_t)bh * TT + n * CC;
    const int tid = threadIdx.x;
    __shared__ float ks[32][64];
    __shared__ float vs[32][64];
    const float Bn = Bsum[cid];
    const int ty = tid >> 4, tx = tid & 15;
    const int tr = tid >> 3, c8 = (tid & 7) << 3;
    float acc[4][4];
#pragma unroll
    for (int i = 0; i < 4; i++)
#pragma unroll
        for (int j = 0; j < 4; j++) acc[i][j] = 0.f;

    for (int ct = 0; ct < 8; ++ct) {
        __syncthreads();
        int trow = ct * 32 + tr;
        float e = expf(Bn - bc[tbase + trow]);
        size_t gb = (tbase + trow) * HD;
        float4 k0 = *(const float4*)&kh[gb + c8];
        float4 k1 = *(const float4*)&kh[gb + c8 + 4];
        *(float4*)&ks[tr][c8]     = make_float4(k0.x * e, k0.y * e, k0.z * e, k0.w * e);
        *(float4*)&ks[tr][c8 + 4] = make_float4(k1.x * e, k1.y * e, k1.z * e, k1.w * e);
        *(float4*)&vs[tr][c8]     = *(const float4*)&vh[gb + c8];
        *(float4*)&vs[tr][c8 + 4] = *(const float4*)&vh[gb + c8 + 4];
        __syncthreads();
#pragma unroll
        for (int kk = 0; kk < 32; ++kk) {
            float4 ka = *(const float4*)&ks[kk][ty * 4];
            float4 vb = *(const float4*)&vs[kk][tx * 4];
            float kaa[4] = {ka.x, ka.y, ka.z, ka.w};
            float vbb[4] = {vb.x, vb.y, vb.z, vb.w};
#pragma unroll
            for (int i = 0; i < 4; i++)
#pragma unroll
                for (int j = 0; j < 4; j++)
                    acc[i][j] += kaa[i] * vbb[j];
        }
    }
    size_t ob = (size_t)cid * HD * HD;
#pragma unroll
    for (int i = 0; i < 4; i++)
        *(float4*)&kv[ob + (size_t)(ty * 4 + i) * HD + tx * 4] =
            make_float4(acc[i][0], acc[i][1], acc[i][2], acc[i][3]);
}

// ---------------- sequential chunk scan ----------------
__global__ __launch_bounds__(256)
void scan_kernel(const float* __restrict__ kv, const float* __restrict__ Bsum,
                 float* __restrict__ Sprev) {
    const int bh = blockIdx.x;
    const int tid = threadIdx.x;
    float4 S[4];
#pragma unroll
    for (int u = 0; u < 4; u++) S[u] = make_float4(0.f, 0.f, 0.f, 0.f);
    for (int n = 0; n < NC; ++n) {
        size_t cb = (size_t)(bh * NC + n) * HD * HD + tid * 16;
#pragma unroll
        for (int u = 0; u < 4; u++) *(float4*)&Sprev[cb + u * 4] = S[u];
        float eB = expf(Bsum[bh * NC + n]);
#pragma unroll
        for (int u = 0; u < 4; u++) {
            float4 kvv = *(const float4*)&kv[cb + u * 4];
            S[u].x = eB * S[u].x + kvv.x;
            S[u].y = eB * S[u].y + kvv.y;
            S[u].z = eB * S[u].z + kvv.z;
            S[u].w = eB * S[u].w + kvv.w;
        }
    }
}

// ---------------- fused intra+cross attention, rmsnorm(64), silu gate ----------------
__global__ __launch_bounds__(256, 1)
void attn_out(const float* __restrict__ qh, const float* __restrict__ kh,
              const float* __restrict__ vh, const float* __restrict__ bc,
              const float* __restrict__ Sprev, const float* __restrict__ gate,
              float* __restrict__ opre) {
    const int cid = blockIdx.x;
    const int bh = cid / NC, n = cid % NC;
    const int b = bh / HH, h = bh % HH;
    const int i = threadIdx.x;
    const size_t tbase = (size_t)bh * TT + n * CC + 0;

    __shared__ float sk[64 * 64];
    __shared__ float sv[64 * 64];
    __shared__ float einv[CC];

    float bci = bc[tbase + i];
    einv[i] = expf(-bci);
    float ebci = expf(bci);

    float4 qv[16];
    {
        const float4* qp = (const float4*)&qh[(tbase + i) * HD];
#pragma unroll
        for (int g = 0; g < 16; g++) {
            float4 q = qp[g];
            qv[g] = make_float4(q.x * ebci, q.y * ebci, q.z * ebci, q.w * ebci);
        }
    }

    {
        size_t sbp = (size_t)cid * HD * HD + i * 16;
#pragma unroll
        for (int u = 0; u < 4; u++)
            *(float4*)&sk[i * 16 + u * 4] = *(const float4*)&Sprev[sbp + u * 4];
    }
    __syncthreads();

    float4 ov[16];
#pragma unroll
    for (int g = 0; g < 16; g++) ov[g] = make_float4(0.f, 0.f, 0.f, 0.f);

#pragma unroll
    for (int mg = 0; mg < 16; ++mg) {
        float qa[4] = {qv[mg].x, qv[mg].y, qv[mg].z, qv[mg].w};
#pragma unroll
        for (int u = 0; u < 4; ++u) {
            float qm = qa[u];
            const float4* Srow = (const float4*)&sk[(mg * 4 + u) * 64];
#pragma unroll
            for (int g = 0; g < 16; ++g) {
                float4 s4 = Srow[g];
                ov[g].x += qm * s4.x; ov[g].y += qm * s4.y;
                ov[g].z += qm * s4.z; ov[g].w += qm * s4.w;
            }
        }
    }

    const int tr = i >> 2, cq = (i & 3);
    for (int tile = 0; tile < 4; ++tile) {
        __syncthreads();
        size_t gk = (tbase + tile * 64 + tr) * HD;
#pragma unroll
        for (int u = 0; u < 4; ++u) {
            int cc = (cq + u * 4) * 4;
            *(float4*)&sk[tr * 64 + cc] = *(const float4*)&kh[gk + cc];
            *(float4*)&sv[tr * 64 + cc] = *(const float4*)&vh[gk + cc];
        }
        __syncthreads();
        int base = tile * 64;
        if (i >= base) {
            int lim = i - base; if (lim > 63) lim = 63;
            for (int tt = 0; tt <= lim; ++tt) {
                const float4* kr = (const float4*)&sk[tt * 64];
                float s = 0.f;
#pragma unroll
                for (int g = 0; g < 16; ++g) {
                    float4 k4 = kr[g];
                    s += qv[g].x * k4.x + qv[g].y * k4.y +
                         qv[g].z * k4.z + qv[g].w * k4.w;
                }
                s *= einv[base + tt];
                const float4* vr = (const float4*)&sv[tt * 64];
#pragma unroll
                for (int g = 0; g < 16; ++g) {
                    float4 v4 = vr[g];
                    ov[g].x += s * v4.x; ov[g].y += s * v4.y;
                    ov[g].z += s * v4.z; ov[g].w += s * v4.w;
                }
            }
        }
    }

    float ss = 0.f;
#pragma unroll
    for (int g = 0; g < 16; ++g)
        ss += ov[g].x * ov[g].x + ov[g].y * ov[g].y +
              ov[g].z * ov[g].z + ov[g].w * ov[g].w;
    float rr = rsqrtf(ss * (1.f / (float)HD) + EPS);

    const size_t trow = (size_t)b * TT + n * CC + i;
    const size_t grow = trow * (4 * DD) + 3 * DD + h * HD;   // gate inside qkvg buffer
    const size_t orow = trow * DD + h * HD;
#pragma unroll
    for (int g = 0; g < 16; ++g) {
        float4 gg = *(const float4*)&gate[grow + g * 4];
        float sx = gg.x / (1.f + expf(-gg.x));
        float sy = gg.y / (1.f + expf(-gg.y));
        float sz = gg.z / (1.f + expf(-gg.z));
        float sw = gg.w / (1.f + expf(-gg.w));
        *(float4*)&opre[orow + g * 4] =
            make_float4(tf32r(sx * ov[g].x * rr), tf32r(sy * ov[g].y * rr),
                        tf32r(sz * ov[g].z * rr), tf32r(sw * ov[g].w * rr));
    }
}

// ---------------- final-output gemm needs a contiguous-src rmsnorm? no: opre is DD-strided.
// The Wo gemm reads opre [BT][DD] contiguous — reuse gemm_tf32 with N=1024.

// ---------------- host launcher ----------------
static float* devptr(const void* symbol) {
    void* p = nullptr;
    cudaGetSymbolAddress(&p, symbol);
    return (float*)p;
}

extern "C" void kernel_launch(void* const* d_in, const int* in_sizes, int n_in,
                              void* d_out, int out_size) {
    const float* x   = (const float*)d_in[0];
    const float* Wq  = (const float*)d_in[1];
    const float* Wk  = (const float*)d_in[2];
    const float* Wv  = (const float*)d_in[3];
    const float* Wg  = (const float*)d_in[4];
    const float* Wgt = (const float*)d_in[5];
    const float* Wo  = (const float*)d_in[6];
    float* out = (float*)d_out;

    float* qkvg = devptr(g_qkvg);
    float* qhp = devptr(g_qh);
    float* khp = devptr(g_kh);
    float* vhp = devptr(g_vh);
    float* xtf = devptr(g_xtf);
    float* wtf = devptr(g_wtf);
    float* gtp = devptr(g_gt);
    float* bcp = devptr(g_bc);
    float* Bp  = devptr(g_Bsum);
    float* kvp = devptr(g_kv);
    float* Sp  = devptr(g_Sprev);

    cudaFuncSetAttribute(gemm_tf32,
        cudaFuncAttributeMaxDynamicSharedMemorySize, SMEM_GEMM);

    // prep: round x, transpose+round weights (wtf[0..3] contiguous => fused N=4096)
    round_tf32<<<(BT * DD / 4) / 256, 256>>>(x, xtf);
    dim3 tg(32, 32);
    round_tr<<<tg, 256>>>(Wq, wtf + 0 * DD * DD);
    round_tr<<<tg, 256>>>(Wk, wtf + 1 * DD * DD);
    round_tr<<<tg, 256>>>(Wv, wtf + 2 * DD * DD);
    round_tr<<<tg, 256>>>(Wg, wtf + 3 * DD * DD);
    round_tr<<<tg, 256>>>(Wo, wtf + 4 * DD * DD);

    // one fused GEMM: [BT,1024] @ [1024,4096] -> qkvg
    dim3 gfused(4 * DD / BN, BT / BM);   // (16, 128)
    gemm_tf32<<<gfused, 256, SMEM_GEMM>>>(xtf, wtf, qkvg, BT, 4 * DD, DD);
    gt_gemm<<<BT / 16, 256>>>(x, Wgt, gtp);

    rmsnorm_reorder<<<BT, 256>>>(qkvg + 0 * DD, qhp, 0.125f);
    rmsnorm_reorder<<<BT, 256>>>(qkvg + 1 * DD, khp, 1.f);
    rmsnorm_reorder<<<BT, 256>>>(qkvg + 2 * DD, vhp, 1.f);

    cumsum_kernel<<<NCH, 256>>>(gtp, bcp, Bp);
    kv_kernel<<<NCH, 256>>>(khp, vhp, bcp, Bp, kvp);
    scan_kernel<<<BH, 256>>>(kvp, Bp, Sp);

    // xtf is dead now; reuse as opre (tf32-rounded attention output)
    attn_out<<<NCH, 256>>>(qhp, khp, vhp, bcp, Sp, qkvg, xtf);

    dim3 gout(DD / BN, BT / BM);         // (4, 128)
    gemm_tf32<<<gout, 256, SMEM_GEMM>>>(xtf, wtf + 4 * DD * DD, out, BT, DD, DD);
}